// round 11
// baseline (speedup 1.0000x reference)
#include <cuda_runtime.h>
#include <cuda_bf16.h>
#include <cstdint>
#include <math.h>

// ---------------------------------------------------------------------------
// minGRU forward on GB300 (compute_103 PTX => classic mma.sync tensor path):
//   hg = W @ x + b   via single-pass TF32 mma.sync GEMM (at the HMMA issue
//                    floor, rt~16/SMSP); X read directly in native [B,D,L]
//                    layout (no transpose prep), tf32 rounding in-register.
//   then per-(b,h) linear scan  h_t = c_t h_{t-1} + v_t
// ---------------------------------------------------------------------------

#define Bsz 8
#define Dd  512
#define Hh  512
#define Ll  8192
#define TWOH 1024

// Scratch (device globals: allocation-free path)
__device__ float g_hg [(size_t)Bsz * TWOH * Ll];   // 268 MB
__device__ float g_w32[(size_t)TWOH * Dd];         // 2 MB  [2H,D] tf32-rounded

// ---------------------------- PTX helpers ----------------------------------
__device__ __forceinline__ uint32_t smem_u32(const void* p) {
    uint32_t a;
    asm("{ .reg .u64 t; cvta.to.shared.u64 t, %1; cvt.u32.u64 %0, t; }"
        : "=r"(a) : "l"(p));
    return a;
}
#define SW128(o) ((o) ^ (((o) >> 3) & 0x70))

__device__ __forceinline__ void cp16(uint32_t dst, const void* src) {
    asm volatile("cp.async.cg.shared.global [%0], [%1], 16;"
                 :: "r"(dst), "l"(__cvta_generic_to_global(src)) : "memory");
}
#define CP_COMMIT() asm volatile("cp.async.commit_group;" ::: "memory")
#define CP_WAIT0()  asm volatile("cp.async.wait_group 0;" ::: "memory")
#define CP_WAIT1()  asm volatile("cp.async.wait_group 1;" ::: "memory")

__device__ __forceinline__ void ldsm_x4(uint32_t &r0, uint32_t &r1,
                                        uint32_t &r2, uint32_t &r3,
                                        uint32_t addr) {
    asm volatile("ldmatrix.sync.aligned.m8n8.x4.shared.b16 {%0,%1,%2,%3}, [%4];"
                 : "=r"(r0), "=r"(r1), "=r"(r2), "=r"(r3) : "r"(addr));
}

__device__ __forceinline__ uint32_t lds32(uint32_t addr) {
    uint32_t v;
    asm volatile("ld.shared.b32 %0, [%1];" : "=r"(v) : "r"(addr));
    return v;
}

__device__ __forceinline__ void mma_tf32(float c[4], const uint32_t a[4],
                                         const uint32_t b[2]) {
    asm volatile(
        "mma.sync.aligned.m16n8k8.row.col.f32.tf32.tf32.f32 "
        "{%0,%1,%2,%3}, {%4,%5,%6,%7}, {%8,%9}, {%0,%1,%2,%3};"
        : "+f"(c[0]), "+f"(c[1]), "+f"(c[2]), "+f"(c[3])
        : "r"(a[0]), "r"(a[1]), "r"(a[2]), "r"(a[3]), "r"(b[0]), "r"(b[1]));
}

__device__ __forceinline__ float tf32r(float x) {
    uint32_t u;
    asm("cvt.rna.tf32.f32 %0, %1;" : "=r"(u) : "f"(x));
    return __uint_as_float(u);
}
__device__ __forceinline__ uint32_t tf32bits(uint32_t xb) {
    uint32_t u;
    asm("cvt.rna.tf32.f32 %0, %1;" : "=r"(u) : "f"(__uint_as_float(xb)));
    return u;
}

// ---------------------------------------------------------------------------
// Prep: round W to tf32 (tiny; X is rounded in-register inside the GEMM)
// ---------------------------------------------------------------------------
__global__ void round_w_kernel(const float* __restrict__ W) {
    int i = (blockIdx.x * 256 + threadIdx.x) * 4;
    float4 v = *(const float4*)(W + i);
    v.x = tf32r(v.x); v.y = tf32r(v.y); v.z = tf32r(v.z); v.w = tf32r(v.w);
    *(float4*)&g_w32[i] = v;
}

// ---------------------------------------------------------------------------
// TF32 mma.sync GEMM: C[b](1024 x 8192) = W(1024x512) @ X[b](512x8192) + bias
// BM=128, BN=128, BK=32. A: swizzled k-major tile (ldmatrix). B: read straight
// from x[B,D,L] as n-major rows into a padded tile [32][128+8] (conflict-free
// LDS.32 fragment loads; bank = (8k+n)%32 all-distinct). tf32 cvt in-register.
// 3-stage cp.async pipeline, 8 warps (4M x 2N), 2 CTAs/SM.
// ---------------------------------------------------------------------------
#define BM 128
#define BN 128
#define BK 32
#define NCHUNK (Dd / BK)            // 16
#define NSTAGE 3
#define BNP       (BN + 8)          // padded row: 136 fp32 = 544 bytes
#define BROW_B    (BNP * 4)         // 544
#define A_BYTES   (BM * 128)        // 16384
#define B_BYTES   (BK * BROW_B)     // 17408
#define STG       (A_BYTES + B_BYTES)   // 33792 (1024-multiple)
#define SMEM_BYTES (NSTAGE * STG + 1024)  // 102400

__global__ __launch_bounds__(256, 2)
void gemm_tc_kernel(const float* __restrict__ X,
                    const float* __restrict__ bias) {
    extern __shared__ char dynsmem[];
    const uint32_t S = (smem_u32(dynsmem) + 1023u) & ~1023u;

    const int tid  = threadIdx.x;
    const int wid  = tid >> 5;
    const int lane = tid & 31;
    const int bz = blockIdx.x;          // batch innermost is irrelevant; keep x=m
    const int m0 = blockIdx.y * BM;
    const int n0 = blockIdx.z * BN;

    // ---- A load mapping: 2 threads per 128B row, 4x cp16 each ----
    const int lrow  = tid >> 1;           // 0..127
    const int lhalf = (tid & 1) * 4;      // 0 or 4
    const float* srcA = g_w32 + (size_t)(m0 + lrow) * Dd;

    // ---- B load mapping: 8 threads per k-row (512B data), 4x cp16 each ----
    const int brow = tid >> 3;            // 0..31 (k within chunk)
    const int bseg = (tid & 7) * 64;      // byte offset within row
    const char* srcB = (const char*)(X + ((size_t)bz * Dd + brow) * Ll + n0) + bseg;

    #define ISSUE_CHUNK(kc)                                                     \
    do {                                                                        \
        const int _st = (kc) % NSTAGE;                                          \
        const uint32_t _sA = S + _st * STG;                                     \
        const uint32_t _sB = _sA + A_BYTES;                                     \
        const int _kbA = (kc) * 128;            /* BK*4 bytes in W row */       \
        const size_t _kbB = (size_t)(kc) * BK * Ll * 4;  /* k-rows in X */      \
        _Pragma("unroll")                                                       \
        for (int j = 0; j < 4; j++) {                                           \
            const int jj = lhalf + j;                                           \
            const uint32_t so = SW128((uint32_t)(lrow * 128 + jj * 16));        \
            cp16(_sA + so, (const char*)srcA + _kbA + jj * 16);                 \
        }                                                                       \
        _Pragma("unroll")                                                       \
        for (int q = 0; q < 4; q++)                                             \
            cp16(_sB + (uint32_t)(brow * BROW_B + bseg + q * 16),               \
                 srcB + _kbB + q * 16);                                         \
        CP_COMMIT();                                                            \
    } while (0)

    // ---- fragment lane addressing ----
    const int mw = (wid & 3) * 32;        // warp M offset
    const int nw = (wid >> 2) * 64;       // warp N offset
    // A via ldmatrix (tf32 as b16 pairs) — unchanged, proven
    const int aRow     = lane & 15;
    const int aColByte = (lane >> 4) * 16;
    uint32_t aByte[2];
    #pragma unroll
    for (int i = 0; i < 2; i++)
        aByte[i] = (uint32_t)((mw + i * 16 + aRow) * 128 + aColByte);
    // B via LDS.32 from padded n-major tile:
    //   b0 = B[k = kbase + (lane&3)][n = nw + j*8 + (lane>>2)], b1 at k+4
    const uint32_t bLane = (uint32_t)((lane & 3) * BROW_B + (nw + (lane >> 2)) * 4);

    float acc[2][8][4];
    #pragma unroll
    for (int i = 0; i < 2; i++)
        #pragma unroll
        for (int j = 0; j < 8; j++)
            #pragma unroll
            for (int q = 0; q < 4; q++) acc[i][j][q] = 0.0f;

    ISSUE_CHUNK(0);
    ISSUE_CHUNK(1);

    for (int kc = 0; kc < NCHUNK; kc++) {
        if (kc == NCHUNK - 1) CP_WAIT0(); else CP_WAIT1();
        __syncthreads();

        if (kc + 2 < NCHUNK) ISSUE_CHUNK(kc + 2);

        const int st = kc % NSTAGE;
        const uint32_t sA = S + st * STG;
        const uint32_t sB = sA + A_BYTES;

        #pragma unroll
        for (int ks = 0; ks < 4; ks++) {           // 4 x k8 = BK
            uint32_t a[2][4];
            #pragma unroll
            for (int i = 0; i < 2; i++)
                ldsm_x4(a[i][0], a[i][1], a[i][2], a[i][3],
                        sA + SW128(aByte[i] + ks * 32));
            uint32_t b[8][2];
            {
                const uint32_t bbase = sB + (uint32_t)(ks * 8) * BROW_B + bLane;
                #pragma unroll
                for (int j = 0; j < 8; j++) {
                    b[j][0] = tf32bits(lds32(bbase + j * 32));
                    b[j][1] = tf32bits(lds32(bbase + j * 32 + 4 * BROW_B));
                }
            }
            #pragma unroll
            for (int i = 0; i < 2; i++)
                #pragma unroll
                for (int j = 0; j < 8; j++)
                    mma_tf32(acc[i][j], a[i], b[j]);
        }
        __syncthreads();
    }

    // ---- epilogue: bias + store ----
    const int mrow = m0 + mw + (lane >> 2);
    const int ncol = n0 + nw + (lane & 3) * 2;
    #pragma unroll
    for (int i = 0; i < 2; i++) {
        const int r0 = mrow + i * 16;
        const float b0 = bias[r0];
        const float b1 = bias[r0 + 8];
        float* C0 = g_hg + ((size_t)bz * TWOH + r0)     * Ll;
        float* C1 = g_hg + ((size_t)bz * TWOH + r0 + 8) * Ll;
        #pragma unroll
        for (int j = 0; j < 8; j++) {
            const int c = ncol + j * 8;
            float2 o0 = { acc[i][j][0] + b0, acc[i][j][1] + b0 };
            float2 o1 = { acc[i][j][2] + b1, acc[i][j][3] + b1 };
            *(float2*)(C0 + c) = o0;
            *(float2*)(C1 + c) = o1;
        }
    }
}

// ---------------------------------------------------------------------------
// Scan: one block per (b,h) lane; 2 blocks/SM; fast-math transcendentals.
// ---------------------------------------------------------------------------
__global__ __launch_bounds__(1024, 2)
void scan_kernel(float* __restrict__ out) {
    const int lane_id = blockIdx.x;
    const int b = lane_id >> 9;
    const int h = lane_id & 511;

    const float* Hrow = g_hg + ((size_t)b * TWOH + h)      * Ll;
    const float* Grow = g_hg + ((size_t)b * TWOH + Hh + h) * Ll;
    float*       Orow = out  + (size_t)lane_id * Ll;

    const int t  = threadIdx.x;
    const int l0 = t * 8;

    float4 hA = *(const float4*)(Hrow + l0);
    float4 hB = *(const float4*)(Hrow + l0 + 4);
    float4 gA = *(const float4*)(Grow + l0);
    float4 gB = *(const float4*)(Grow + l0 + 4);

    float hv[8] = {hA.x, hA.y, hA.z, hA.w, hB.x, hB.y, hB.z, hB.w};
    float gv[8] = {gA.x, gA.y, gA.z, gA.w, gB.x, gB.y, gB.z, gB.w};

    float c[8], v[8];
    #pragma unroll
    for (int i = 0; i < 8; i++) {
        const float g  = gv[i];
        const float eg = __expf(g);
        const float ci = 1.0f / (1.0f + eg);          // sigmoid(-g)
        const float si = 1.0f - ci;                   // sigmoid(g)
        const float z  = hv[i];
        const float gf = (z >= 0.0f) ? (z + 1.0f) : __expf(z);
        c[i] = ci;
        v[i] = si * gf;
    }

    float C = c[0], V = v[0];
    #pragma unroll
    for (int i = 1; i < 8; i++) {
        V = fmaf(c[i], V, v[i]);
        C *= c[i];
    }

    const int lane = t & 31, warp = t >> 5;
    #pragma unroll
    for (int d = 1; d < 32; d <<= 1) {
        float Cp = __shfl_up_sync(0xFFFFFFFFu, C, d);
        float Vp = __shfl_up_sync(0xFFFFFFFFu, V, d);
        if (lane >= d) { V = fmaf(C, Vp, V); C = C * Cp; }
    }

    __shared__ float sC[32], sV[32];
    if (lane == 31) { sC[warp] = C; sV[warp] = V; }
    __syncthreads();

    if (warp == 0) {
        float Cw = sC[lane], Vw = sV[lane];
        #pragma unroll
        for (int d = 1; d < 32; d <<= 1) {
            float Cp = __shfl_up_sync(0xFFFFFFFFu, Cw, d);
            float Vp = __shfl_up_sync(0xFFFFFFFFu, Vw, d);
            if (lane >= d) { Vw = fmaf(Cw, Vp, Vw); Cw = Cw * Cp; }
        }
        sC[lane] = Cw;
        sV[lane] = Vw;
    }
    __syncthreads();

    float bV = (warp == 0) ? 0.0f : sV[warp - 1];

    float eC = __shfl_up_sync(0xFFFFFFFFu, C, 1);
    float eV = __shfl_up_sync(0xFFFFFFFFu, V, 1);
    if (lane == 0) { eC = 1.0f; eV = 0.0f; }

    float acc = fmaf(eC, bV, eV);

    float o[8];
    #pragma unroll
    for (int i = 0; i < 8; i++) {
        acc  = fmaf(c[i], acc, v[i]);
        o[i] = acc;
    }
    float4 oA = {o[0], o[1], o[2], o[3]};
    float4 oB = {o[4], o[5], o[6], o[7]};
    *(float4*)(Orow + l0)     = oA;
    *(float4*)(Orow + l0 + 4) = oB;
}

// ---------------------------------------------------------------------------
extern "C" void kernel_launch(void* const* d_in, const int* in_sizes, int n_in,
                              void* d_out, int out_size) {
    const float* x = nullptr;
    const float* W = nullptr;
    const float* bias = nullptr;
    for (int i = 0; i < n_in; i++) {
        const int s = in_sizes[i];
        if      (s == Bsz * Dd * Ll) x    = (const float*)d_in[i];
        else if (s == TWOH * Dd)     W    = (const float*)d_in[i];
        else if (s == TWOH)          bias = (const float*)d_in[i];
    }

    static int smem_set = 0;
    if (!smem_set) {
        cudaFuncSetAttribute(gemm_tc_kernel,
                             cudaFuncAttributeMaxDynamicSharedMemorySize,
                             SMEM_BYTES);
        smem_set = 1;
    }

    round_w_kernel<<<TWOH * Dd / (256 * 4), 256>>>(W);
    gemm_tc_kernel<<<dim3(Bsz, TWOH / BM, Ll / BN), 256, SMEM_BYTES>>>(x, bias);
    scan_kernel<<<Bsz * Hh, 1024>>>((float*)d_out);
}